// round 1
// baseline (speedup 1.0000x reference)
#include <cuda_runtime.h>
#include <math.h>

// Problem constants
constexpr int N_OSC   = 2048;
constexpr int N_SAMP  = 16384;
constexpr int LAT     = 32;

// Tiling
constexpr int OSC_CHUNK  = 128;
constexpr int SAMP_CHUNK = 1024;
constexpr int N_OSC_BLK  = N_OSC  / OSC_CHUNK;   // 16
constexpr int N_SAMP_BLK = N_SAMP / SAMP_CHUNK;  // 16
constexpr int THREADS    = 256;
constexpr int SPT        = SAMP_CHUNK / THREADS; // 4 samples per thread

// Partial signals: [osc_block][sample]  (1 MB, fully overwritten each launch)
__device__ float g_scratch[N_OSC_BLK * N_SAMP];

// -----------------------------------------------------------------------------
// Main kernel: each block = 128 oscillators x 1024 samples.
// Phase closed form (inclusive prefix of piecewise-linear upsampled freq):
//   pre   (i < 256):        P = (i+1)*fp0            -> C_0 + (i-255)*fp0
//   seg k (m = 0..511):     P = C_k + (m+1)*fp[k] + (m+1)^2/1024 * (fp[k+1]-fp[k])
//   post  (i >= 16128):     P = C_31 + (i-16127)*fp[31]
// with C_k = 256*fp0 + sum_{j<k} 256*(fp[j]+fp[j+1])   (computed in fp64)
// signal contribution = sin(pi32 * P) * amp,  amp via same lo/hi/w interpolation.
// -----------------------------------------------------------------------------
__global__ __launch_bounds__(THREADS, 1)
void osc_kernel(const float* __restrict__ latent) {
    __shared__ float2 s_fpap[OSC_CHUNK][LAT];  // (freq, amp) params   32 KB
    __shared__ float  s_base[OSC_CHUNK][LAT];  // C_k prefix table     16 KB

    const int tid      = threadIdx.x;
    const int sampBase = blockIdx.x * SAMP_CHUNK;
    const int oscBase  = blockIdx.y * OSC_CHUNK;

    // ---- per-oscillator precompute (one thread per oscillator) ----
    if (tid < OSC_CHUNK) {
        const int o = tid;
        const float4* fr = reinterpret_cast<const float4*>(
            latent + (size_t)(N_OSC + oscBase + o) * LAT);
        const float4* ar = reinterpret_cast<const float4*>(
            latent + (size_t)(oscBase + o) * LAT);
        float fp[LAT];
#pragma unroll
        for (int q = 0; q < LAT / 4; ++q) {
            float4 fv = fr[q];
            float4 av = ar[q];
            float f0 = fabsf(fv.x), f1 = fabsf(fv.y), f2 = fabsf(fv.z), f3 = fabsf(fv.w);
            fp[4*q+0] = f0; fp[4*q+1] = f1; fp[4*q+2] = f2; fp[4*q+3] = f3;
            s_fpap[o][4*q+0] = make_float2(f0, fabsf(av.x));
            s_fpap[o][4*q+1] = make_float2(f1, fabsf(av.y));
            s_fpap[o][4*q+2] = make_float2(f2, fabsf(av.z));
            s_fpap[o][4*q+3] = make_float2(f3, fabsf(av.w));
        }
        double c = 256.0 * (double)fp[0];
#pragma unroll
        for (int k = 0; k < LAT; ++k) {
            s_base[o][k] = (float)c;
            if (k < LAT - 1) c += 256.0 * ((double)fp[k] + (double)fp[k + 1]);
        }
    }
    __syncthreads();

    // ---- per-thread sample-position constants (oscillator independent) ----
    int   lo[SPT], hi[SPT], kb[SPT];
    float c1[SPT], c2[SPT], w[SPT], acc[SPT];
#pragma unroll
    for (int s = 0; s < SPT; ++s) {
        const int i = sampBase + tid + s * THREADS;
        acc[s] = 0.0f;
        if (i < 256) {                       // pre region: P = C_0 + (i-255)*fp0
            kb[s] = 0; lo[s] = 0; hi[s] = 0;
            c1[s] = (float)(i - 255); c2[s] = 0.0f; w[s] = 0.0f;
        } else if (i >= 16128) {             // post region
            kb[s] = 31; lo[s] = 31; hi[s] = 31;
            c1[s] = (float)(i - 16127); c2[s] = 0.0f; w[s] = 0.0f;
        } else {                             // linear segment k, offset m
            const int k = (i - 256) >> 9;
            const int m = (i - 256) & 511;
            kb[s] = k; lo[s] = k; hi[s] = k + 1;
            const float mp1 = (float)(m + 1);
            c1[s] = mp1;
            c2[s] = mp1 * mp1 * (1.0f / 1024.0f);
            w[s]  = ((float)m + 0.5f) * (1.0f / 512.0f);
        }
    }

    const float PI_F = 3.14159274101257324f;  // float32(np.pi)

    // ---- main loop: all smem loads are warp-uniform (broadcast) ----
#pragma unroll 2
    for (int o = 0; o < OSC_CHUNK; ++o) {
#pragma unroll
        for (int s = 0; s < SPT; ++s) {
            const float2 plo  = s_fpap[o][lo[s]];
            const float2 phi  = s_fpap[o][hi[s]];
            const float  base = s_base[o][kb[s]];
            // inclusive prefix of upsampled freq
            float P = fmaf(c2[s], phi.x - plo.x, fmaf(c1[s], plo.x, base));
            // reduce P mod 2 exactly (phase period of sin(pi*P) is 2 in P)
            float r = fmaf(-2.0f, rintf(0.5f * P), P);   // r in [-1, 1]
            float sv = __sinf(r * PI_F);
            float amp = fmaf(w[s], phi.y - plo.y, plo.y);
            acc[s] = fmaf(sv, amp, acc[s]);
        }
    }

#pragma unroll
    for (int s = 0; s < SPT; ++s)
        g_scratch[blockIdx.y * N_SAMP + sampBase + tid + s * THREADS] = acc[s];
}

// -----------------------------------------------------------------------------
// Epilogue 1: deterministic 16-way reduction over oscillator blocks + mean.
// -----------------------------------------------------------------------------
__global__ void reduce_kernel(float* __restrict__ out) {
    const int i = blockIdx.x * blockDim.x + threadIdx.x;  // 0..16383
    float s = 0.0f;
#pragma unroll
    for (int b = 0; b < N_OSC_BLK; ++b) s += g_scratch[b * N_SAMP + i];
    out[i] = s * (1.0f / (float)N_OSC);
}

// -----------------------------------------------------------------------------
// Epilogue 2: |latent| passthroughs.
//   out[16384 : 16384+65536]        = |latent[65536:131072]|  (freq_params)
//   out[16384+65536 : 16384+131072] = |latent[0:65536]|       (amp_params)
// -----------------------------------------------------------------------------
__global__ void params_kernel(const float* __restrict__ latent, float* __restrict__ out) {
    const int i = blockIdx.x * blockDim.x + threadIdx.x;  // 0..131071
    const int HALF = N_OSC * LAT;                          // 65536
    const float v = fabsf(latent[i]);
    const int dst = (i < HALF) ? (N_SAMP + HALF + i) : (N_SAMP + i - HALF);
    out[dst] = v;
}

extern "C" void kernel_launch(void* const* d_in, const int* in_sizes, int n_in,
                              void* d_out, int out_size) {
    // latent is the input with 2*N_OSC*LAT elements (x is a 1-element dummy)
    const float* latent = (const float*)d_in[n_in - 1];
    for (int i = 0; i < n_in; ++i) {
        if (in_sizes[i] == 2 * N_OSC * LAT) { latent = (const float*)d_in[i]; break; }
    }
    float* out = (float*)d_out;

    dim3 grid(N_SAMP_BLK, N_OSC_BLK);
    osc_kernel<<<grid, THREADS>>>(latent);
    reduce_kernel<<<N_SAMP / 256, 256>>>(out);
    params_kernel<<<(2 * N_OSC * LAT) / 256, 256>>>(latent, out);
}

// round 2
// speedup vs baseline: 1.0468x; 1.0468x over previous
#include <cuda_runtime.h>
#include <math.h>

constexpr int N_OSC  = 2048;
constexpr int N_SAMP = 16384;
constexpr int LAT    = 32;
constexpr int HALF   = N_OSC * LAT;               // 65536

constexpr int OSC_CHUNK  = 32;
constexpr int SAMP_CHUNK = 1024;
constexpr int THREADS    = 256;
constexpr int SPT        = 4;                      // contiguous samples per thread
constexpr int N_OSC_BLK  = N_OSC / OSC_CHUNK;      // 64
constexpr int N_SAMP_BLK = N_SAMP / SAMP_CHUNK;    // 16

// Precomputed per-(osc,k): (fp[k], fp[k+1]-fp[k], ap[k], ap[k+1]-ap[k]) and C_k/2
__device__ float4 g_pack[N_OSC * LAT];
__device__ float  g_base[N_OSC * LAT];
// Partial signals per oscillator block: 64 x 16384 floats = 4 MB
__device__ float  g_scratch[N_OSC_BLK * N_SAMP];

// -----------------------------------------------------------------------------
// Prep: abs params, segment deltas, and fp64-accurate halved prefix table
//   C_k = 256*fp0 + sum_{j<k} 256*(fp[j]+fp[j+1]);  store C_k/2
//   k=31 entry has df=da=0 (used only by the post region, constant extrapolation)
// -----------------------------------------------------------------------------
__global__ void prep_kernel(const float* __restrict__ latent) {
    const int o = blockIdx.x * blockDim.x + threadIdx.x;
    if (o >= N_OSC) return;
    float fp[LAT], ap[LAT];
    const float4* fr = reinterpret_cast<const float4*>(latent + (size_t)(N_OSC + o) * LAT);
    const float4* ar = reinterpret_cast<const float4*>(latent + (size_t)o * LAT);
#pragma unroll
    for (int q = 0; q < LAT / 4; ++q) {
        float4 f = fr[q], a = ar[q];
        fp[4*q+0] = fabsf(f.x); fp[4*q+1] = fabsf(f.y);
        fp[4*q+2] = fabsf(f.z); fp[4*q+3] = fabsf(f.w);
        ap[4*q+0] = fabsf(a.x); ap[4*q+1] = fabsf(a.y);
        ap[4*q+2] = fabsf(a.z); ap[4*q+3] = fabsf(a.w);
    }
    double c = 256.0 * (double)fp[0];
#pragma unroll
    for (int k = 0; k < LAT; ++k) {
        const float df = (k < LAT - 1) ? (fp[k+1] - fp[k]) : 0.0f;
        const float da = (k < LAT - 1) ? (ap[k+1] - ap[k]) : 0.0f;
        g_pack[o * LAT + k] = make_float4(fp[k], df, ap[k], da);
        g_base[o * LAT + k] = (float)(0.5 * c);
        if (k < LAT - 1) c += 256.0 * ((double)fp[k] + (double)fp[k+1]);
    }
}

// -----------------------------------------------------------------------------
// Main: block = 32 oscillators x 1024 samples. Each thread: 4 CONTIGUOUS samples
// (segment boundaries are 4-aligned, so all 4 share segment k -> per-osc loads
// hoist out of the sample loop: 1 LDS.128 + 1 LDS.32 per oscillator).
// Half-phase closed form: P2 = C_k/2 + c1h*fp[k] + c2h*df,  sin(pi*P) = sin(2pi*r)
// with r = P2 - rint(P2) in [-0.5, 0.5] (exact subtraction).
// -----------------------------------------------------------------------------
__global__ __launch_bounds__(THREADS, 4)
void osc_kernel() {
    __shared__ float4 s_pack[OSC_CHUNK * LAT];   // 16 KB
    __shared__ float  s_base[OSC_CHUNK * LAT];   //  4 KB

    const int tid      = threadIdx.x;
    const int oscBase  = blockIdx.y * OSC_CHUNK;
    const int sampBase = blockIdx.x * SAMP_CHUNK;

#pragma unroll
    for (int j = tid; j < OSC_CHUNK * LAT; j += THREADS) {
        s_pack[j] = g_pack[oscBase * LAT + j];
        s_base[j] = g_base[oscBase * LAT + j];
    }
    __syncthreads();

    const int i0 = sampBase + tid * SPT;
    int k;
    float c1h[SPT], c2h[SPT], w[SPT];
    if (i0 < 256) {                              // pre: P2 = C0/2 + 0.5*(i-255)*fp0
        k = 0;
#pragma unroll
        for (int s = 0; s < SPT; ++s) { c1h[s] = 0.5f * (float)(i0 + s - 255); c2h[s] = 0.0f; w[s] = 0.0f; }
    } else if (i0 >= 16128) {                    // post: P2 = C31/2 + 0.5*(i-16127)*fp31
        k = 31;
#pragma unroll
        for (int s = 0; s < SPT; ++s) { c1h[s] = 0.5f * (float)(i0 + s - 16127); c2h[s] = 0.0f; w[s] = 0.0f; }
    } else {                                     // segment k, offset m
        k = (i0 - 256) >> 9;
        const int m0 = (i0 - 256) & 511;
#pragma unroll
        for (int s = 0; s < SPT; ++s) {
            const float mp1 = (float)(m0 + s + 1);
            c1h[s] = 0.5f * mp1;
            c2h[s] = mp1 * mp1 * (1.0f / 2048.0f);
            w[s]   = ((float)(m0 + s) + 0.5f) * (1.0f / 512.0f);
        }
    }

    float acc[SPT] = {0.0f, 0.0f, 0.0f, 0.0f};
    const float TWO_PI = 6.28318530717958648f;

#pragma unroll 4
    for (int o = 0; o < OSC_CHUNK; ++o) {
        const float4 p  = s_pack[o * LAT + k];   // (flo, df, alo, da)
        const float  bh = s_base[o * LAT + k];
#pragma unroll
        for (int s = 0; s < SPT; ++s) {
            const float P2  = fmaf(c2h[s], p.y, fmaf(c1h[s], p.x, bh));
            const float r   = P2 - rintf(P2);            // exact, in [-0.5, 0.5]
            const float sv  = __sinf(r * TWO_PI);
            const float amp = fmaf(w[s], p.w, p.z);
            acc[s] = fmaf(sv, amp, acc[s]);
        }
    }

    *reinterpret_cast<float4*>(&g_scratch[blockIdx.y * N_SAMP + i0]) =
        make_float4(acc[0], acc[1], acc[2], acc[3]);
}

// -----------------------------------------------------------------------------
// Fused epilogue: deterministic 64-way partial reduction + mean for the signal,
// and |latent| passthroughs for the two param outputs.
//   out[0:16384]                 = mean signal
//   out[16384:16384+65536]       = |latent[65536:131072]|   (freq_params)
//   out[16384+65536:...]         = |latent[0:65536]|        (amp_params)
// -----------------------------------------------------------------------------
__global__ void epilogue_kernel(const float* __restrict__ latent, float* __restrict__ out) {
    const int i = blockIdx.x * blockDim.x + threadIdx.x;
    if (i < N_SAMP) {
        float a0 = 0.0f, a1 = 0.0f, a2 = 0.0f, a3 = 0.0f;
#pragma unroll
        for (int b = 0; b < N_OSC_BLK; b += 4) {
            a0 += g_scratch[(b + 0) * N_SAMP + i];
            a1 += g_scratch[(b + 1) * N_SAMP + i];
            a2 += g_scratch[(b + 2) * N_SAMP + i];
            a3 += g_scratch[(b + 3) * N_SAMP + i];
        }
        out[i] = ((a0 + a1) + (a2 + a3)) * (1.0f / (float)N_OSC);
    } else if (i < N_SAMP + 2 * HALF) {
        const int idx = i - N_SAMP;
        const int src = (idx < HALF) ? (HALF + idx) : (idx - HALF);
        out[i] = fabsf(latent[src]);
    }
}

extern "C" void kernel_launch(void* const* d_in, const int* in_sizes, int n_in,
                              void* d_out, int out_size) {
    const float* latent = (const float*)d_in[n_in - 1];
    for (int i = 0; i < n_in; ++i) {
        if (in_sizes[i] == 2 * HALF) { latent = (const float*)d_in[i]; break; }
    }
    float* out = (float*)d_out;

    prep_kernel<<<(N_OSC + 255) / 256, 256>>>(latent);
    dim3 grid(N_SAMP_BLK, N_OSC_BLK);
    osc_kernel<<<grid, THREADS>>>();
    epilogue_kernel<<<(N_SAMP + 2 * HALF + 255) / 256, 256>>>(latent, out);
}